// round 11
// baseline (speedup 1.0000x reference)
#include <cuda_runtime.h>
#include <cfloat>
#include <math.h>

// Problem constants (fixed by the benchmark)
#define BB   2
#define CC   2
#define NN   1024
#define HH   8
#define FF   64
#define FIN2 (HH*FF)          // 512
#define NSL  (BB*CC*HH)       // 32 attention slices
#define L2E  1.4426950408889634f

// ---------------- scratch (device globals: allocation-free) ----------------
__device__ unsigned int g_mask[BB*NN*(NN/32)];            // packed valid-edge bits (incl self loops)
__device__ float g_hp[(size_t)NSL*NN*FF];                 // h_prime for current layer
__device__ float g_s [NSL*NN];                            // src scores
__device__ float g_d [NSL*NN];                            // dst scores
__device__ float g_rml[NSL*NN];                           // rowmax * log2(e)
__device__ float g_x1[(size_t)BB*CC*NN*FIN2];             // layer-1 output (elu, head-flattened)
__device__ float g_o2[(size_t)NSL*NN*FF];                 // layer-2 attention output (pre head-mean)

// ---------------- helpers ----------------
union f4u { float4 f; unsigned long long u[2]; float e[4]; };

__device__ __forceinline__ unsigned long long pack2(float a, float b){
    unsigned long long r;
    asm("mov.b64 %0, {%1,%2};" : "=l"(r) : "f"(a), "f"(b));
    return r;
}
__device__ __forceinline__ void ffma2(unsigned long long &d, unsigned long long a, unsigned long long b){
    asm("fma.rn.f32x2 %0, %1, %2, %0;" : "+l"(d) : "l"(a), "l"(b));
}
__device__ __forceinline__ float ex2f(float x){
    float r; asm("ex2.approx.f32 %0, %1;" : "=f"(r) : "f"(x)); return r;
}
__device__ __forceinline__ void cpasync16(unsigned smem, const void* g){
    asm volatile("cp.async.cg.shared.global [%0], [%1], 16;" :: "r"(smem), "l"(g));
}
__device__ __forceinline__ void cpasync_commit(){ asm volatile("cp.async.commit_group;"); }
__device__ __forceinline__ void cpasync_wait0(){ asm volatile("cp.async.wait_group 0;"); }

// ---------------- kernel 1: pack adjacency (+self loops) into bitmask ----------------
__global__ void pack_mask_kernel(const int* __restrict__ adj){
    int n = blockIdx.x, b = blockIdx.y, m = threadIdx.x;   // block of 1024 threads
    bool valid = (adj[((size_t)b*NN + n)*NN + m] != 0) || (m == n);
    unsigned bits = __ballot_sync(0xffffffffu, valid);
    if ((m & 31) == 0) g_mask[((size_t)b*NN + n)*32 + (m >> 5)] = bits;
}

// ---------------- kernel 2: h_prime = x @ w  (+ tanh -> s,d scores) ----------------
// grid (NSL, NN/64), block 256. Thread tile 4 rows x 4 feats, f32x2 FMAs.
template<int FIN, bool FROMX1>
__global__ __launch_bounds__(256, 3) void gemm_sd_kernel(
    const float* __restrict__ xin, const float* __restrict__ w,
    const float* __restrict__ a_src, const float* __restrict__ a_dst)
{
    __shared__ float xs[64*64];     // [n][k]
    __shared__ float ws[64*64];     // [k][f]
    __shared__ float as_s[64], ad_s[64];

    const int sl = blockIdx.x, n0 = blockIdx.y*64;
    const int b = sl/(CC*HH), c = (sl/HH)%CC, h = sl%HH;
    const int tid = threadIdx.x, lane = tid & 31;
    const int tx = tid & 15, ty = tid >> 4;        // feats 4tx.., rows 4ty..

    const float* x = FROMX1 ? (const float*)g_x1 : xin;
    const float* xbase = x + ((size_t)(b*CC + c)*NN + n0)*FIN;
    const float* wbase = w + (size_t)(c*HH + h)*FIN*FF;

    if (tid < 64){
        int ch = (c*HH + h)*FF;
        as_s[tid] = a_src[ch + tid];
        ad_s[tid] = a_dst[ch + tid];
    }

    f4u acc[4];
    #pragma unroll
    for (int j = 0; j < 4; j++){ acc[j].u[0] = 0ull; acc[j].u[1] = 0ull; }

    for (int kc = 0; kc < FIN/64; kc++){
        __syncthreads();
        // stage x tile [64n x 64k] (coalesced float4)
        #pragma unroll
        for (int p = 0; p < 4; p++){
            int n = (tid >> 4) + 16*p;
            ((float4*)xs)[n*16 + (tid & 15)] =
                *(const float4*)&xbase[(size_t)n*FIN + kc*64 + 4*(tid & 15)];
        }
        // stage w tile [64k x 64f] (contiguous)
        const float4* wsrc = (const float4*)(wbase + (size_t)kc*64*FF);
        #pragma unroll
        for (int q = 0; q < 4; q++) ((float4*)ws)[tid + 256*q] = wsrc[tid + 256*q];
        __syncthreads();

        const float4* xs4 = (const float4*)xs;
        const float4* ws4 = (const float4*)ws;
        #pragma unroll
        for (int kk = 0; kk < 16; kk++){
            f4u xr[4];
            #pragma unroll
            for (int j = 0; j < 4; j++) xr[j].f = xs4[(4*ty + j)*16 + kk];
            #pragma unroll
            for (int i = 0; i < 4; i++){
                f4u wv; wv.f = ws4[(4*kk + i)*16 + tx];
                #pragma unroll
                for (int j = 0; j < 4; j++){
                    unsigned long long xx = pack2(xr[j].e[i], xr[j].e[i]);
                    ffma2(acc[j].u[0], wv.u[0], xx);
                    ffma2(acc[j].u[1], wv.u[1], xx);
                }
            }
        }
    }

    // epilogue: write h_prime + tanh-weighted scores
    #pragma unroll
    for (int j = 0; j < 4; j++){
        const int n = n0 + 4*ty + j;
        *(float4*)&g_hp[((size_t)sl*NN + n)*FF + 4*tx] = acc[j].f;
        float sp = 0.f, dp = 0.f;
        #pragma unroll
        for (int i = 0; i < 4; i++){
            float t = tanhf(acc[j].e[i]);
            sp = fmaf(t, as_s[4*tx + i], sp);
            dp = fmaf(t, ad_s[4*tx + i], dp);
        }
        #pragma unroll
        for (int o = 8; o; o >>= 1){
            sp += __shfl_xor_sync(0xffffffffu, sp, o);
            dp += __shfl_xor_sync(0xffffffffu, dp, o);
        }
        if ((lane & 15) == 0){ g_s[sl*NN + n] = sp; g_d[sl*NN + n] = dp; }
    }
}

// ---------------- kernel 3: exact row max (leaky is monotone => leaky(s + dmax)) ----------------
// grid (NSL, NN/128), block 256 (8 warps x 16 rows).
__global__ __launch_bounds__(256) void rowmax_kernel(){
    __shared__ float d_sw[1024];                 // d rotated for conflict-free column scans
    const int sl = blockIdx.x, n0 = blockIdx.y*128;
    const int b = sl/(CC*HH);
    const int tid = threadIdx.x, lane = tid & 31, wrp = tid >> 5;

    for (int i = tid; i < 1024; i += 256){
        int w = i >> 5, j = i & 31;
        d_sw[(w << 5) + ((j + w) & 31)] = g_d[sl*NN + i];
    }
    __syncthreads();

    const unsigned* mb = g_mask + (size_t)b*NN*32;
    for (int r = 0; r < 16; r++){
        const int n = n0 + wrp*16 + r;
        unsigned word = mb[(size_t)n*32 + lane];
        float dm = -FLT_MAX;
        #pragma unroll
        for (int i = 0; i < 32; i++){
            float v = d_sw[(lane << 5) + ((i + lane) & 31)];
            if ((word >> i) & 1u) dm = fmaxf(dm, v);
        }
        #pragma unroll
        for (int o = 16; o; o >>= 1) dm = fmaxf(dm, __shfl_xor_sync(0xffffffffu, dm, o));
        if (lane == 0){
            float s = g_s[sl*NN + n];
            float r0 = s + dm; r0 = (r0 >= 0.f) ? r0 : 0.2f*r0;   // leaky(max) = max(leaky)
            g_rml[sl*NN + n] = r0 * L2E;
        }
    }
}

// ---------------- kernel 4: masked softmax + P @ h_prime (single pass, no rescale) ----------------
// grid (NSL, NN/64), block 256, 4 CTAs/SM. 64 rows x 64 feats per block, m-tile 64.
// Scores: warp w owns rows 8w..8w+7 (mask words fetched coalesced by lanes 0-15).
// Accumulate: SPLIT-K over thread halves (kh = tid>>7); 128 thread-cells own
// 4 rows (strided: 16j + ty) x 8 feats each. Per kk (4 k): 4 e-LDS.128 (bank-
// spread broadcast, 1 wf) + 8 hp-LDS.128 (1 wf) + 64 ffma2 -> 12 wf / 128 MACs,
// half of the previous wavefront cost. Halves combined once at the end via smem.
template<bool LAYER1>
__global__ __launch_bounds__(256, 4) void attn_kernel(){
    __shared__ float hp_s[64*64];                // [m][f] 16 KB (reused for kh-combine)
    __shared__ float e_s[64*68];                 // [row][m] padded, 17 KB
    __shared__ float d_s[1024];
    __shared__ float s_s[64];
    __shared__ float rml_s[64];
    __shared__ float linv_s[64];

    const int sl = blockIdx.x, n0 = blockIdx.y*64;
    const int b = sl/(CC*HH), c = (sl/HH)%CC, h = sl%HH;
    const int tid = threadIdx.x, lane = tid & 31, wrp = tid >> 5;
    const int hid = tid & 127;                   // cell id within k-half
    const int tx = hid & 7;                      // feats 8*tx .. 8*tx+7
    const int ty = hid >> 3;                     // rows 16j + ty, j=0..3
    const int kh = tid >> 7;                     // k-half (0: k 0..31, 1: k 32..63 of tile)
    const int row0 = wrp*8;

    for (int i = tid; i < 1024; i += 256) d_s[i] = g_d[sl*NN + i];
    if (tid < 64){
        s_s[tid]   = g_s  [sl*NN + n0 + tid];
        rml_s[tid] = g_rml[sl*NN + n0 + tid];
    }

    float lsum[8];
    #pragma unroll
    for (int r = 0; r < 8; r++) lsum[r] = 0.f;

    f4u acc[4][2];                               // [row j][feat half]
    #pragma unroll
    for (int j = 0; j < 4; j++){
        acc[j][0].u[0] = acc[j][0].u[1] = 0ull;
        acc[j][1].u[0] = acc[j][1].u[1] = 0ull;
    }

    const unsigned* mbase = g_mask + ((size_t)b*NN + n0)*32;
    const unsigned hp_smem = (unsigned)__cvta_generic_to_shared(hp_s);

    __syncthreads();                             // d_s/s_s/rml_s ready

    for (int t = 0; t < 16; t++){
        const int m0 = t*64;

        // issue async copy of h_prime tile (overlaps with score phase below)
        const float4* hsrc = (const float4*)(g_hp + ((size_t)sl*NN + m0)*FF);
        #pragma unroll
        for (int q = 0; q < 4; q++)
            cpasync16(hp_smem + (tid + 256*q)*16, hsrc + tid + 256*q);
        cpasync_commit();

        // coalesced mask fetch: lanes 0..15 hold 8 rows x 2 words for this warp
        unsigned mword = 0u;
        if (lane < 16)
            mword = mbase[(size_t)(row0 + (lane >> 1))*32 + t*2 + (lane & 1)];

        // --- score phase ---
        const float d0 = d_s[m0 + lane];
        const float d1 = d_s[m0 + lane + 32];
        #pragma unroll
        for (int r = 0; r < 8; r++){
            const int row = row0 + r;
            unsigned mwa = __shfl_sync(0xffffffffu, mword, 2*r);
            unsigned mwb = __shfl_sync(0xffffffffu, mword, 2*r + 1);
            float s = s_s[row], rml = rml_s[row];
            float x0 = s + d0; x0 = (x0 >= 0.f) ? x0 : 0.2f*x0;    // leaky_relu(0.2)
            float x1 = s + d1; x1 = (x1 >= 0.f) ? x1 : 0.2f*x1;
            float e0 = ((mwa >> lane) & 1u) ? ex2f(fmaf(x0, L2E, -rml)) : 0.f;
            float e1 = ((mwb >> lane) & 1u) ? ex2f(fmaf(x1, L2E, -rml)) : 0.f;
            lsum[r] += e0 + e1;
            e_s[row*68 + lane]      = e0;
            e_s[row*68 + lane + 32] = e1;
        }

        cpasync_wait0();
        __syncthreads();                         // e_s + hp_s ready

        // --- accumulate phase: split-k register GEMM (this half: k = 32*kh .. +31) ---
        const float4* hp4 = (const float4*)hp_s;
        const float4* e4  = (const float4*)e_s;  // row stride 17 float4
        #pragma unroll
        for (int kk = 0; kk < 8; kk++){
            const int ka = 8*kh + kk;            // float4 index along k
            f4u ev[4];
            #pragma unroll
            for (int j = 0; j < 4; j++) ev[j].f = e4[(16*j + ty)*17 + ka];
            #pragma unroll
            for (int i = 0; i < 4; i++){
                f4u h0, h1;
                h0.f = hp4[(4*ka + i)*16 + 2*tx];
                h1.f = hp4[(4*ka + i)*16 + 2*tx + 1];
                #pragma unroll
                for (int j = 0; j < 4; j++){
                    unsigned long long ee = pack2(ev[j].e[i], ev[j].e[i]);
                    ffma2(acc[j][0].u[0], h0.u[0], ee);
                    ffma2(acc[j][0].u[1], h0.u[1], ee);
                    ffma2(acc[j][1].u[0], h1.u[0], ee);
                    ffma2(acc[j][1].u[1], h1.u[1], ee);
                }
            }
        }
        __syncthreads();                         // protect hp_s/e_s before next tile
    }

    // reduce row sums (per-lane partials) and invert
    #pragma unroll
    for (int r = 0; r < 8; r++){
        float v = lsum[r];
        #pragma unroll
        for (int o = 16; o; o >>= 1) v += __shfl_xor_sync(0xffffffffu, v, o);
        if (lane == 0) linv_s[row0 + r] = 1.f / v;
    }

    // combine the two k-halves through smem (hp_s is free now)
    f4u* comb = (f4u*)hp_s;
    if (kh == 1){
        #pragma unroll
        for (int j = 0; j < 4; j++){
            comb[hid*8 + 2*j]     = acc[j][0];
            comb[hid*8 + 2*j + 1] = acc[j][1];
        }
    }
    __syncthreads();                             // comb + linv_s ready

    if (kh == 0){
        #pragma unroll
        for (int j = 0; j < 4; j++){
            const int row = 16*j + ty, n = n0 + row;
            const float inv = linv_s[row];
            f4u p0 = comb[hid*8 + 2*j], p1 = comb[hid*8 + 2*j + 1];
            f4u o0, o1;
            #pragma unroll
            for (int i = 0; i < 4; i++){
                o0.e[i] = (acc[j][0].e[i] + p0.e[i]) * inv;
                o1.e[i] = (acc[j][1].e[i] + p1.e[i]) * inv;
            }
            if (LAYER1){
                #pragma unroll
                for (int i = 0; i < 4; i++){
                    o0.e[i] = (o0.e[i] > 0.f) ? o0.e[i] : expm1f(o0.e[i]);   // elu
                    o1.e[i] = (o1.e[i] > 0.f) ? o1.e[i] : expm1f(o1.e[i]);
                }
                float* dst = &g_x1[((size_t)(b*CC + c)*NN + n)*FIN2 + h*FF + 8*tx];
                *(float4*)dst       = o0.f;
                *(float4*)(dst + 4) = o1.f;
            } else {
                float* dst = &g_o2[((size_t)sl*NN + n)*FF + 8*tx];
                *(float4*)dst       = o0.f;
                *(float4*)(dst + 4) = o1.f;
            }
        }
    }
}

// ---------------- kernel 5: mean over heads ----------------
__global__ void reduce_mean_kernel(float* __restrict__ out){
    int idx = blockIdx.x*blockDim.x + threadIdx.x;          // B*C*N*F = 262144
    int f  = idx & 63;
    int nn = (idx >> 6) & (NN - 1);
    int bc = idx >> 16;                                     // NN*FF = 65536
    float sum = 0.f;
    #pragma unroll
    for (int h = 0; h < HH; h++)
        sum += g_o2[(((size_t)bc*HH + h)*NN + nn)*FF + f];
    out[idx] = sum * (1.f / HH);
}

// ---------------- launch ----------------
extern "C" void kernel_launch(void* const* d_in, const int* in_sizes, int n_in,
                              void* d_out, int out_size)
{
    const float* x   = (const float*)d_in[0];
    const int*   adj = (const int*)  d_in[1];
    const float* w1  = (const float*)d_in[2];
    const float* as1 = (const float*)d_in[3];
    const float* ad1 = (const float*)d_in[4];
    const float* w2  = (const float*)d_in[5];
    const float* as2 = (const float*)d_in[6];
    const float* ad2 = (const float*)d_in[7];
    float* out = (float*)d_out;

    pack_mask_kernel<<<dim3(NN, BB), 1024>>>(adj);

    gemm_sd_kernel<64,  false><<<dim3(NSL, 16), 256>>>(x, w1, as1, ad1);
    rowmax_kernel<<<dim3(NSL, 8), 256>>>();
    attn_kernel<true ><<<dim3(NSL, 16), 256>>>();

    gemm_sd_kernel<FIN2, true><<<dim3(NSL, 16), 256>>>(nullptr, w2, as2, ad2);
    rowmax_kernel<<<dim3(NSL, 8), 256>>>();
    attn_kernel<false><<<dim3(NSL, 16), 256>>>();

    reduce_mean_kernel<<<(BB*CC*NN*FF)/256, 256>>>(out);
}

// round 13
// speedup vs baseline: 1.5395x; 1.5395x over previous
#include <cuda_runtime.h>
#include <cfloat>
#include <math.h>
#include <cstdint>

// Problem constants (fixed by the benchmark)
#define BB   2
#define CC   2
#define NN   1024
#define HH   8
#define FF   64
#define FIN2 (HH*FF)          // 512
#define NSL  (BB*CC*HH)       // 32 attention slices
#define L2E  1.4426950408889634f

// ---------------- scratch (device globals: allocation-free) ----------------
__device__ unsigned int g_mask[BB*NN*(NN/32)];            // packed valid-edge bits (incl self loops)
__device__ float g_hp[(size_t)NSL*NN*FF];                 // h_prime for current layer
__device__ float g_s [NSL*NN];                            // src scores
__device__ float g_d [NSL*NN];                            // dst scores
__device__ float g_rml[NSL*NN];                           // rowmax * log2(e)
__device__ float g_x1[(size_t)BB*CC*NN*FIN2];             // layer-1 output (elu, head-flattened)
__device__ float g_o2[(size_t)NSL*NN*FF];                 // layer-2 attention output (pre head-mean)

// ---------------- helpers ----------------
union f4u { float4 f; unsigned long long u[2]; float e[4]; };

__device__ __forceinline__ unsigned long long pack2(float a, float b){
    unsigned long long r;
    asm("mov.b64 %0, {%1,%2};" : "=l"(r) : "f"(a), "f"(b));
    return r;
}
__device__ __forceinline__ void ffma2(unsigned long long &d, unsigned long long a, unsigned long long b){
    asm("fma.rn.f32x2 %0, %1, %2, %0;" : "+l"(d) : "l"(a), "l"(b));
}
__device__ __forceinline__ float ex2f(float x){
    float r; asm("ex2.approx.f32 %0, %1;" : "=f"(r) : "f"(x)); return r;
}
__device__ __forceinline__ void cpasync16(unsigned smem, const void* g){
    asm volatile("cp.async.cg.shared.global [%0], [%1], 16;" :: "r"(smem), "l"(g));
}
__device__ __forceinline__ void cpasync_commit(){ asm volatile("cp.async.commit_group;"); }
__device__ __forceinline__ void cpasync_wait0(){ asm volatile("cp.async.wait_group 0;"); }

// m16n8k8 tf32 HMMA (sm_80+ path; legal on plain sm_103 target)
__device__ __forceinline__ void mma_tf32(float* d, const uint32_t* a, uint32_t b0, uint32_t b1){
    asm volatile(
        "mma.sync.aligned.m16n8k8.row.col.f32.tf32.tf32.f32 "
        "{%0,%1,%2,%3}, {%4,%5,%6,%7}, {%8,%9}, {%0,%1,%2,%3};"
        : "+f"(d[0]), "+f"(d[1]), "+f"(d[2]), "+f"(d[3])
        : "r"(a[0]), "r"(a[1]), "r"(a[2]), "r"(a[3]), "r"(b0), "r"(b1));
}

// 3xtf32 split: hi keeps 10 explicit mantissa bits (exactly tf32), lo = x - hi
__device__ __forceinline__ void split32(float x, uint32_t &hi, uint32_t &lo){
    uint32_t xb = __float_as_uint(x);
    hi = xb & 0xFFFFE000u;
    lo = __float_as_uint(x - __uint_as_float(hi));
}

// ---------------- kernel 1: pack adjacency (+self loops) into bitmask ----------------
__global__ void pack_mask_kernel(const int* __restrict__ adj){
    int n = blockIdx.x, b = blockIdx.y, m = threadIdx.x;   // block of 1024 threads
    bool valid = (adj[((size_t)b*NN + n)*NN + m] != 0) || (m == n);
    unsigned bits = __ballot_sync(0xffffffffu, valid);
    if ((m & 31) == 0) g_mask[((size_t)b*NN + n)*32 + (m >> 5)] = bits;
}

// ---------------- kernel 2: h_prime = x @ w  (+ tanh -> s,d scores) ----------------
template<int FIN, bool FROMX1>
__global__ __launch_bounds__(256, 3) void gemm_sd_kernel(
    const float* __restrict__ xin, const float* __restrict__ w,
    const float* __restrict__ a_src, const float* __restrict__ a_dst)
{
    __shared__ float xs[64*64];     // [n][k]
    __shared__ float ws[64*64];     // [k][f]
    __shared__ float as_s[64], ad_s[64];

    const int sl = blockIdx.x, n0 = blockIdx.y*64;
    const int b = sl/(CC*HH), c = (sl/HH)%CC, h = sl%HH;
    const int tid = threadIdx.x, lane = tid & 31;
    const int tx = tid & 15, ty = tid >> 4;

    const float* x = FROMX1 ? (const float*)g_x1 : xin;
    const float* xbase = x + ((size_t)(b*CC + c)*NN + n0)*FIN;
    const float* wbase = w + (size_t)(c*HH + h)*FIN*FF;

    if (tid < 64){
        int ch = (c*HH + h)*FF;
        as_s[tid] = a_src[ch + tid];
        ad_s[tid] = a_dst[ch + tid];
    }

    f4u acc[4];
    #pragma unroll
    for (int j = 0; j < 4; j++){ acc[j].u[0] = 0ull; acc[j].u[1] = 0ull; }

    for (int kc = 0; kc < FIN/64; kc++){
        __syncthreads();
        #pragma unroll
        for (int p = 0; p < 4; p++){
            int n = (tid >> 4) + 16*p;
            ((float4*)xs)[n*16 + (tid & 15)] =
                *(const float4*)&xbase[(size_t)n*FIN + kc*64 + 4*(tid & 15)];
        }
        const float4* wsrc = (const float4*)(wbase + (size_t)kc*64*FF);
        #pragma unroll
        for (int q = 0; q < 4; q++) ((float4*)ws)[tid + 256*q] = wsrc[tid + 256*q];
        __syncthreads();

        const float4* xs4 = (const float4*)xs;
        const float4* ws4 = (const float4*)ws;
        #pragma unroll
        for (int kk = 0; kk < 16; kk++){
            f4u xr[4];
            #pragma unroll
            for (int j = 0; j < 4; j++) xr[j].f = xs4[(4*ty + j)*16 + kk];
            #pragma unroll
            for (int i = 0; i < 4; i++){
                f4u wv; wv.f = ws4[(4*kk + i)*16 + tx];
                #pragma unroll
                for (int j = 0; j < 4; j++){
                    unsigned long long xx = pack2(xr[j].e[i], xr[j].e[i]);
                    ffma2(acc[j].u[0], wv.u[0], xx);
                    ffma2(acc[j].u[1], wv.u[1], xx);
                }
            }
        }
    }

    #pragma unroll
    for (int j = 0; j < 4; j++){
        const int n = n0 + 4*ty + j;
        *(float4*)&g_hp[((size_t)sl*NN + n)*FF + 4*tx] = acc[j].f;
        float sp = 0.f, dp = 0.f;
        #pragma unroll
        for (int i = 0; i < 4; i++){
            float t = tanhf(acc[j].e[i]);
            sp = fmaf(t, as_s[4*tx + i], sp);
            dp = fmaf(t, ad_s[4*tx + i], dp);
        }
        #pragma unroll
        for (int o = 8; o; o >>= 1){
            sp += __shfl_xor_sync(0xffffffffu, sp, o);
            dp += __shfl_xor_sync(0xffffffffu, dp, o);
        }
        if ((lane & 15) == 0){ g_s[sl*NN + n] = sp; g_d[sl*NN + n] = dp; }
    }
}

// ---------------- kernel 3: exact row max (leaky is monotone => leaky(s + dmax)) ----------------
__global__ __launch_bounds__(256) void rowmax_kernel(){
    __shared__ float d_sw[1024];
    const int sl = blockIdx.x, n0 = blockIdx.y*128;
    const int b = sl/(CC*HH);
    const int tid = threadIdx.x, lane = tid & 31, wrp = tid >> 5;

    for (int i = tid; i < 1024; i += 256){
        int w = i >> 5, j = i & 31;
        d_sw[(w << 5) + ((j + w) & 31)] = g_d[sl*NN + i];
    }
    __syncthreads();

    const unsigned* mb = g_mask + (size_t)b*NN*32;
    for (int r = 0; r < 16; r++){
        const int n = n0 + wrp*16 + r;
        unsigned word = mb[(size_t)n*32 + lane];
        float dm = -FLT_MAX;
        #pragma unroll
        for (int i = 0; i < 32; i++){
            float v = d_sw[(lane << 5) + ((i + lane) & 31)];
            if ((word >> i) & 1u) dm = fmaxf(dm, v);
        }
        #pragma unroll
        for (int o = 16; o; o >>= 1) dm = fmaxf(dm, __shfl_xor_sync(0xffffffffu, dm, o));
        if (lane == 0){
            float s = g_s[sl*NN + n];
            float r0 = s + dm; r0 = (r0 >= 0.f) ? r0 : 0.2f*r0;
            g_rml[sl*NN + n] = r0 * L2E;
        }
    }
}

// ---------------- kernel 4: masked softmax + P @ h_prime via mma.sync tf32 ----------------
// grid (NSL, NN/64), block 256 (8 warps), 4 CTAs/SM. 64 rows x 64 feats, m-tile 64.
// Score phase: warp w owns rows 8w..8w+7 (identical to R9). MMA phase: warp w owns a
// 16-row x 32-feat output tile (rg = w&3 rows, fh = w>>2 feats); A = e (smem, stride 68),
// B = hp (smem, stride 72 -> conflict-free fragment loads). 3xtf32 for fp32 accuracy.
template<bool LAYER1>
__global__ __launch_bounds__(256, 4) void attn_mma_kernel(){
    __shared__ float hp_s[64*72];                // [m(k)][f], padded stride 72 (18 KB)
    __shared__ float e_s[64*68];                 // [row][m], padded stride 68 (17 KB)
    __shared__ float d_s[1024];
    __shared__ float s_s[64];
    __shared__ float rml_s[64];
    __shared__ float linv_s[64];

    const int sl = blockIdx.x, n0 = blockIdx.y*64;
    const int b = sl/(CC*HH), c = (sl/HH)%CC, h = sl%HH;
    const int tid = threadIdx.x, lane = tid & 31, wrp = tid >> 5;
    const int row0 = wrp*8;
    const int gid = lane >> 2, t4 = lane & 3;    // mma fragment coords
    const int rg = wrp & 3, fh = wrp >> 2;       // warp tile: rows 16rg.., feats 32fh..

    for (int i = tid; i < 1024; i += 256) d_s[i] = g_d[sl*NN + i];
    if (tid < 64){
        s_s[tid]   = g_s  [sl*NN + n0 + tid];
        rml_s[tid] = g_rml[sl*NN + n0 + tid];
    }

    float lsum[8];
    #pragma unroll
    for (int r = 0; r < 8; r++) lsum[r] = 0.f;

    float dacc[4][4];                            // [n-tile][mma d-regs]
    #pragma unroll
    for (int nt = 0; nt < 4; nt++)
        #pragma unroll
        for (int i = 0; i < 4; i++) dacc[nt][i] = 0.f;

    const unsigned* mbase = g_mask + ((size_t)b*NN + n0)*32;
    const unsigned hp_smem = (unsigned)__cvta_generic_to_shared(hp_s);
    const float* hpsl = g_hp + (size_t)sl*NN*FF;

    __syncthreads();                             // d_s/s_s/rml_s ready

    for (int t = 0; t < 16; t++){
        const int m0 = t*64;

        // async copy of hp tile into padded [m][72] layout (overlaps score phase)
        #pragma unroll
        for (int q = 0; q < 4; q++){
            const int cid = tid + 256*q;         // 1024 chunks of 16B
            const int m = cid >> 4, j = cid & 15;
            cpasync16(hp_smem + (unsigned)(m*288 + j*16),
                      hpsl + (size_t)(m0 + m)*FF + 4*j);
        }
        cpasync_commit();

        // coalesced mask fetch: lanes 0..15 hold 8 rows x 2 words for this warp
        unsigned mword = 0u;
        if (lane < 16)
            mword = mbase[(size_t)(row0 + (lane >> 1))*32 + t*2 + (lane & 1)];

        // --- score phase (rows 8w..8w+7) ---
        const float d0 = d_s[m0 + lane];
        const float d1 = d_s[m0 + lane + 32];
        #pragma unroll
        for (int r = 0; r < 8; r++){
            const int row = row0 + r;
            unsigned mwa = __shfl_sync(0xffffffffu, mword, 2*r);
            unsigned mwb = __shfl_sync(0xffffffffu, mword, 2*r + 1);
            float s = s_s[row], rml = rml_s[row];
            float x0 = s + d0; x0 = (x0 >= 0.f) ? x0 : 0.2f*x0;    // leaky_relu(0.2)
            float x1 = s + d1; x1 = (x1 >= 0.f) ? x1 : 0.2f*x1;
            float e0 = ((mwa >> lane) & 1u) ? ex2f(fmaf(x0, L2E, -rml)) : 0.f;
            float e1 = ((mwb >> lane) & 1u) ? ex2f(fmaf(x1, L2E, -rml)) : 0.f;
            lsum[r] += e0 + e1;
            e_s[row*68 + lane]      = e0;
            e_s[row*68 + lane + 32] = e1;
        }

        cpasync_wait0();
        __syncthreads();                         // e_s + hp_s ready

        // --- mma phase: 16x32 warp tile, k=64, 3xtf32 ---
        const float* ea = e_s + (16*rg + gid)*68;
        #pragma unroll
        for (int kk = 0; kk < 8; kk++){
            // A fragment (rows gid/gid+8, cols 8kk+t4 / +4) — conflict-free (4gid+t4)
            float a0 = ea[8*kk + t4];
            float a1 = ea[8*68 + 8*kk + t4];
            float a2 = ea[8*kk + t4 + 4];
            float a3 = ea[8*68 + 8*kk + t4 + 4];
            uint32_t ahi[4], alo[4];
            split32(a0, ahi[0], alo[0]);
            split32(a1, ahi[1], alo[1]);
            split32(a2, ahi[2], alo[2]);
            split32(a3, ahi[3], alo[3]);

            const float* bp = hp_s + (8*kk + t4)*72 + 32*fh + gid;
            #pragma unroll
            for (int nt = 0; nt < 4; nt++){
                // B fragment (k rows t4/t4+4, n col gid) — conflict-free (8t4+gid)
                float b0 = bp[8*nt];
                float b1 = bp[4*72 + 8*nt];
                uint32_t bh0, bl0, bh1, bl1;
                split32(b0, bh0, bl0);
                split32(b1, bh1, bl1);
                mma_tf32(dacc[nt], ahi, bh0, bh1);
                mma_tf32(dacc[nt], ahi, bl0, bl1);
                mma_tf32(dacc[nt], alo, bh0, bh1);
            }
        }
        __syncthreads();                         // protect hp_s/e_s before next tile
    }

    // reduce row sums (per-lane partials) and invert
    #pragma unroll
    for (int r = 0; r < 8; r++){
        float v = lsum[r];
        #pragma unroll
        for (int o = 16; o; o >>= 1) v += __shfl_xor_sync(0xffffffffu, v, o);
        if (lane == 0) linv_s[row0 + r] = 1.f / v;
    }
    __syncthreads();

    // epilogue: scale by 1/l, (elu,) store. d-regs: (gid,2t4),(gid,2t4+1),(gid+8,..)
    const int r0 = 16*rg + gid, r1 = r0 + 8;
    const float inv0 = linv_s[r0];
    const float inv1 = linv_s[r1];
    const int ng0 = n0 + r0, ng1 = n0 + r1;
    #pragma unroll
    for (int nt = 0; nt < 4; nt++){
        const int col = 32*fh + 8*nt + 2*t4;
        float v00 = dacc[nt][0]*inv0, v01 = dacc[nt][1]*inv0;
        float v10 = dacc[nt][2]*inv1, v11 = dacc[nt][3]*inv1;
        if (LAYER1){
            v00 = (v00 > 0.f) ? v00 : expm1f(v00);
            v01 = (v01 > 0.f) ? v01 : expm1f(v01);
            v10 = (v10 > 0.f) ? v10 : expm1f(v10);
            v11 = (v11 > 0.f) ? v11 : expm1f(v11);
            float* base = &g_x1[((size_t)(b*CC + c)*NN)*FIN2 + h*FF + col];
            *(float2*)(base + (size_t)ng0*FIN2) = make_float2(v00, v01);
            *(float2*)(base + (size_t)ng1*FIN2) = make_float2(v10, v11);
        } else {
            float* base = &g_o2[((size_t)sl*NN)*FF + col];
            *(float2*)(base + (size_t)ng0*FF) = make_float2(v00, v01);
            *(float2*)(base + (size_t)ng1*FF) = make_float2(v10, v11);
        }
    }
}

// ---------------- kernel 5: mean over heads ----------------
__global__ void reduce_mean_kernel(float* __restrict__ out){
    int idx = blockIdx.x*blockDim.x + threadIdx.x;          // B*C*N*F = 262144
    int f  = idx & 63;
    int nn = (idx >> 6) & (NN - 1);
    int bc = idx >> 16;
    float sum = 0.f;
    #pragma unroll
    for (int h = 0; h < HH; h++)
        sum += g_o2[(((size_t)bc*HH + h)*NN + nn)*FF + f];
    out[idx] = sum * (1.f / HH);
}

// ---------------- launch ----------------
extern "C" void kernel_launch(void* const* d_in, const int* in_sizes, int n_in,
                              void* d_out, int out_size)
{
    const float* x   = (const float*)d_in[0];
    const int*   adj = (const int*)  d_in[1];
    const float* w1  = (const float*)d_in[2];
    const float* as1 = (const float*)d_in[3];
    const float* ad1 = (const float*)d_in[4];
    const float* w2  = (const float*)d_in[5];
    const float* as2 = (const float*)d_in[6];
    const float* ad2 = (const float*)d_in[7];
    float* out = (float*)d_out;

    pack_mask_kernel<<<dim3(NN, BB), 1024>>>(adj);

    gemm_sd_kernel<64,  false><<<dim3(NSL, 16), 256>>>(x, w1, as1, ad1);
    rowmax_kernel<<<dim3(NSL, 8), 256>>>();
    attn_mma_kernel<true ><<<dim3(NSL, 16), 256>>>();

    gemm_sd_kernel<FIN2, true><<<dim3(NSL, 16), 256>>>(nullptr, w2, as2, ad2);
    rowmax_kernel<<<dim3(NSL, 8), 256>>>();
    attn_mma_kernel<false><<<dim3(NSL, 16), 256>>>();

    reduce_mean_kernel<<<(BB*CC*NN*FF)/256, 256>>>(out);
}

// round 14
// speedup vs baseline: 1.8003x; 1.1694x over previous
#include <cuda_runtime.h>
#include <cfloat>
#include <math.h>
#include <cstdint>

// Problem constants (fixed by the benchmark)
#define BB   2
#define CC   2
#define NN   1024
#define HH   8
#define FF   64
#define FIN2 (HH*FF)          // 512
#define NSL  (BB*CC*HH)       // 32 attention slices
#define L2E  1.4426950408889634f

// ---------------- scratch (device globals: allocation-free) ----------------
__device__ unsigned int g_mask[BB*NN*(NN/32)];            // packed valid-edge bits (incl self loops)
__device__ float g_hp[(size_t)NSL*NN*FF];                 // h_prime for current layer
__device__ float g_s [NSL*NN];                            // src scores
__device__ float g_d [NSL*NN];                            // dst scores
__device__ float g_rml[NSL*NN];                           // rowmax * log2(e)
__device__ float g_x1[(size_t)BB*CC*NN*FIN2];             // layer-1 output (elu, head-flattened)
__device__ float g_o2[(size_t)NSL*NN*FF];                 // layer-2 attention output (pre head-mean)

// ---------------- helpers ----------------
union f4u { float4 f; unsigned long long u[2]; float e[4]; };

__device__ __forceinline__ unsigned long long pack2(float a, float b){
    unsigned long long r;
    asm("mov.b64 %0, {%1,%2};" : "=l"(r) : "f"(a), "f"(b));
    return r;
}
__device__ __forceinline__ void ffma2(unsigned long long &d, unsigned long long a, unsigned long long b){
    asm("fma.rn.f32x2 %0, %1, %2, %0;" : "+l"(d) : "l"(a), "l"(b));
}
__device__ __forceinline__ float ex2f(float x){
    float r; asm("ex2.approx.f32 %0, %1;" : "=f"(r) : "f"(x)); return r;
}

// pack two floats -> bf16x2 (hi_elem goes to upper half, lo_elem to lower half)
__device__ __forceinline__ uint32_t packbf2(float hi_elem, float lo_elem){
    uint32_t r;
    asm("cvt.rn.bf16x2.f32 %0, %1, %2;" : "=r"(r) : "f"(hi_elem), "f"(lo_elem));
    return r;
}

// m16n8k16 bf16 HMMA (sm_80+ path; legal on plain sm_103 target)
__device__ __forceinline__ void mma_bf16(float* d, const uint32_t* a, uint32_t b0, uint32_t b1){
    asm volatile(
        "mma.sync.aligned.m16n8k16.row.col.f32.bf16.bf16.f32 "
        "{%0,%1,%2,%3}, {%4,%5,%6,%7}, {%8,%9}, {%0,%1,%2,%3};"
        : "+f"(d[0]), "+f"(d[1]), "+f"(d[2]), "+f"(d[3])
        : "r"(a[0]), "r"(a[1]), "r"(a[2]), "r"(a[3]), "r"(b0), "r"(b1));
}

// ---------------- kernel 1: pack adjacency (+self loops) into bitmask ----------------
__global__ void pack_mask_kernel(const int* __restrict__ adj){
    int n = blockIdx.x, b = blockIdx.y, m = threadIdx.x;   // block of 1024 threads
    bool valid = (adj[((size_t)b*NN + n)*NN + m] != 0) || (m == n);
    unsigned bits = __ballot_sync(0xffffffffu, valid);
    if ((m & 31) == 0) g_mask[((size_t)b*NN + n)*32 + (m >> 5)] = bits;
}

// ---------------- kernel 2: h_prime = x @ w  (+ tanh -> s,d scores) ----------------
template<int FIN, bool FROMX1>
__global__ __launch_bounds__(256, 3) void gemm_sd_kernel(
    const float* __restrict__ xin, const float* __restrict__ w,
    const float* __restrict__ a_src, const float* __restrict__ a_dst)
{
    __shared__ float xs[64*64];     // [n][k]
    __shared__ float ws[64*64];     // [k][f]
    __shared__ float as_s[64], ad_s[64];

    const int sl = blockIdx.x, n0 = blockIdx.y*64;
    const int b = sl/(CC*HH), c = (sl/HH)%CC, h = sl%HH;
    const int tid = threadIdx.x, lane = tid & 31;
    const int tx = tid & 15, ty = tid >> 4;

    const float* x = FROMX1 ? (const float*)g_x1 : xin;
    const float* xbase = x + ((size_t)(b*CC + c)*NN + n0)*FIN;
    const float* wbase = w + (size_t)(c*HH + h)*FIN*FF;

    if (tid < 64){
        int ch = (c*HH + h)*FF;
        as_s[tid] = a_src[ch + tid];
        ad_s[tid] = a_dst[ch + tid];
    }

    f4u acc[4];
    #pragma unroll
    for (int j = 0; j < 4; j++){ acc[j].u[0] = 0ull; acc[j].u[1] = 0ull; }

    for (int kc = 0; kc < FIN/64; kc++){
        __syncthreads();
        #pragma unroll
        for (int p = 0; p < 4; p++){
            int n = (tid >> 4) + 16*p;
            ((float4*)xs)[n*16 + (tid & 15)] =
                *(const float4*)&xbase[(size_t)n*FIN + kc*64 + 4*(tid & 15)];
        }
        const float4* wsrc = (const float4*)(wbase + (size_t)kc*64*FF);
        #pragma unroll
        for (int q = 0; q < 4; q++) ((float4*)ws)[tid + 256*q] = wsrc[tid + 256*q];
        __syncthreads();

        const float4* xs4 = (const float4*)xs;
        const float4* ws4 = (const float4*)ws;
        #pragma unroll
        for (int kk = 0; kk < 16; kk++){
            f4u xr[4];
            #pragma unroll
            for (int j = 0; j < 4; j++) xr[j].f = xs4[(4*ty + j)*16 + kk];
            #pragma unroll
            for (int i = 0; i < 4; i++){
                f4u wv; wv.f = ws4[(4*kk + i)*16 + tx];
                #pragma unroll
                for (int j = 0; j < 4; j++){
                    unsigned long long xx = pack2(xr[j].e[i], xr[j].e[i]);
                    ffma2(acc[j].u[0], wv.u[0], xx);
                    ffma2(acc[j].u[1], wv.u[1], xx);
                }
            }
        }
    }

    #pragma unroll
    for (int j = 0; j < 4; j++){
        const int n = n0 + 4*ty + j;
        *(float4*)&g_hp[((size_t)sl*NN + n)*FF + 4*tx] = acc[j].f;
        float sp = 0.f, dp = 0.f;
        #pragma unroll
        for (int i = 0; i < 4; i++){
            float t = tanhf(acc[j].e[i]);
            sp = fmaf(t, as_s[4*tx + i], sp);
            dp = fmaf(t, ad_s[4*tx + i], dp);
        }
        #pragma unroll
        for (int o = 8; o; o >>= 1){
            sp += __shfl_xor_sync(0xffffffffu, sp, o);
            dp += __shfl_xor_sync(0xffffffffu, dp, o);
        }
        if ((lane & 15) == 0){ g_s[sl*NN + n] = sp; g_d[sl*NN + n] = dp; }
    }
}

// ---------------- kernel 3: exact row max (leaky is monotone => leaky(s + dmax)) ----------------
__global__ __launch_bounds__(256) void rowmax_kernel(){
    __shared__ float d_sw[1024];
    const int sl = blockIdx.x, n0 = blockIdx.y*128;
    const int b = sl/(CC*HH);
    const int tid = threadIdx.x, lane = tid & 31, wrp = tid >> 5;

    for (int i = tid; i < 1024; i += 256){
        int w = i >> 5, j = i & 31;
        d_sw[(w << 5) + ((j + w) & 31)] = g_d[sl*NN + i];
    }
    __syncthreads();

    const unsigned* mb = g_mask + (size_t)b*NN*32;
    for (int r = 0; r < 16; r++){
        const int n = n0 + wrp*16 + r;
        unsigned word = mb[(size_t)n*32 + lane];
        float dm = -FLT_MAX;
        #pragma unroll
        for (int i = 0; i < 32; i++){
            float v = d_sw[(lane << 5) + ((i + lane) & 31)];
            if ((word >> i) & 1u) dm = fmaxf(dm, v);
        }
        #pragma unroll
        for (int o = 16; o; o >>= 1) dm = fmaxf(dm, __shfl_xor_sync(0xffffffffu, dm, o));
        if (lane == 0){
            float s = g_s[sl*NN + n];
            float r0 = s + dm; r0 = (r0 >= 0.f) ? r0 : 0.2f*r0;
            g_rml[sl*NN + n] = r0 * L2E;
        }
    }
}

// ---------------- kernel 4: masked softmax + P @ h_prime via mma.sync bf16 (3-term) ----------------
// grid (NSL, NN/64), block 256 (8 warps), 4 CTAs/SM. 64 rows x 64 feats, m-tile 64.
// All bf16 hi/lo splits hoisted OUT of the MMA loop:
//  - e: score phase computes k-pairs (lane -> k=2*lane,2*lane+1) and stores packed bf16x2
//    hi/lo into ehi/elo [row][kp], stride 36 (fragment loads 4*gid+t4: conflict-free).
//  - hp: per-tile conversion pass builds B-layout bhi/blo [f][kp] (pairs along k=m),
//    coalesced LDG.32 reads, STS.128 stores (phase-conflict-free at stride 36).
// MMA loop: pure LDS.32 + m16n8k16 HMMA, zero ALU. 3 MMAs per (kk,nt): hihi+hilo+lohi.
template<bool LAYER1>
__global__ __launch_bounds__(256, 4) void attn_mma_kernel(){
    __shared__ uint32_t ehi[64*36], elo[64*36];     // A operand pairs (9 KB each)
    __shared__ uint32_t bhi_s[64*36], blo_s[64*36]; // B operand pairs (9 KB each)
    __shared__ float d_s[1024];
    __shared__ float s_s[64];
    __shared__ float rml_s[64];
    __shared__ float linv_s[64];

    const int sl = blockIdx.x, n0 = blockIdx.y*64;
    const int b = sl/(CC*HH), c = (sl/HH)%CC, h = sl%HH;
    const int tid = threadIdx.x, lane = tid & 31, wrp = tid >> 5;
    const int row0 = wrp*8;
    const int gid = lane >> 2, t4 = lane & 3;    // mma fragment coords
    const int rg = wrp & 3, fh = wrp >> 2;       // warp tile: rows 16rg.., feats 32fh..

    for (int i = tid; i < 1024; i += 256) d_s[i] = g_d[sl*NN + i];
    if (tid < 64){
        s_s[tid]   = g_s  [sl*NN + n0 + tid];
        rml_s[tid] = g_rml[sl*NN + n0 + tid];
    }

    float lsum[8];
    #pragma unroll
    for (int r = 0; r < 8; r++) lsum[r] = 0.f;

    float dacc[4][4];                            // [n-tile][mma d-regs]
    #pragma unroll
    for (int nt = 0; nt < 4; nt++)
        #pragma unroll
        for (int i = 0; i < 4; i++) dacc[nt][i] = 0.f;

    const unsigned* mbase = g_mask + ((size_t)b*NN + n0)*32;
    const float* hpsl = g_hp + (size_t)sl*NN*FF;

    // conversion-pass cell coords: 512 cells = 64 f x 8 kp-quads, 2 cells/thread
    const int cf0 = tid & 63, ckq0 = tid >> 6;           // cell 0
    const int cf1 = cf0, ckq1 = ckq0 + 4;                // cell 1 (tid + 256)

    __syncthreads();                             // d_s/s_s/rml_s ready

    for (int t = 0; t < 16; t++){
        const int m0 = t*64;

        // ---- hp -> bf16 hi/lo B tiles (coalesced LDG.32; latencies overlap converts) ----
        float v0[8], v1[8];
        #pragma unroll
        for (int mm = 0; mm < 8; mm++)
            v0[mm] = hpsl[(size_t)(m0 + 8*ckq0 + mm)*FF + cf0];
        #pragma unroll
        for (int mm = 0; mm < 8; mm++)
            v1[mm] = hpsl[(size_t)(m0 + 8*ckq1 + mm)*FF + cf1];
        {
            uint32_t hi[4], lo[4];
            #pragma unroll
            for (int p = 0; p < 4; p++){
                hi[p] = packbf2(v0[2*p+1], v0[2*p]);
                float h0 = __uint_as_float(hi[p] << 16);
                float h1 = __uint_as_float(hi[p] & 0xFFFF0000u);
                lo[p] = packbf2(v0[2*p+1] - h1, v0[2*p] - h0);
            }
            *(uint4*)&bhi_s[cf0*36 + 4*ckq0] = make_uint4(hi[0], hi[1], hi[2], hi[3]);
            *(uint4*)&blo_s[cf0*36 + 4*ckq0] = make_uint4(lo[0], lo[1], lo[2], lo[3]);
            #pragma unroll
            for (int p = 0; p < 4; p++){
                hi[p] = packbf2(v1[2*p+1], v1[2*p]);
                float h0 = __uint_as_float(hi[p] << 16);
                float h1 = __uint_as_float(hi[p] & 0xFFFF0000u);
                lo[p] = packbf2(v1[2*p+1] - h1, v1[2*p] - h0);
            }
            *(uint4*)&bhi_s[cf1*36 + 4*ckq1] = make_uint4(hi[0], hi[1], hi[2], hi[3]);
            *(uint4*)&blo_s[cf1*36 + 4*ckq1] = make_uint4(lo[0], lo[1], lo[2], lo[3]);
        }

        // coalesced mask fetch: lanes 0..15 hold 8 rows x 2 words for this warp
        unsigned mword = 0u;
        if (lane < 16)
            mword = mbase[(size_t)(row0 + (lane >> 1))*32 + t*2 + (lane & 1)];

        // --- score phase: lane owns k-pair (2*lane, 2*lane+1); writes packed bf16 hi/lo ---
        const float2 dd = *(const float2*)&d_s[m0 + 2*lane];
        const unsigned shft = (2*lane) & 31;
        #pragma unroll
        for (int r = 0; r < 8; r++){
            const int row = row0 + r;
            unsigned mwa = __shfl_sync(0xffffffffu, mword, 2*r);
            unsigned mwb = __shfl_sync(0xffffffffu, mword, 2*r + 1);
            unsigned sel = (lane < 16) ? mwa : mwb;
            unsigned bits = (sel >> shft) & 3u;
            float s = s_s[row], rml = rml_s[row];
            float x0 = s + dd.x; x0 = (x0 >= 0.f) ? x0 : 0.2f*x0;  // leaky_relu(0.2)
            float x1 = s + dd.y; x1 = (x1 >= 0.f) ? x1 : 0.2f*x1;
            float e0 = (bits & 1u) ? ex2f(fmaf(x0, L2E, -rml)) : 0.f;
            float e1 = (bits & 2u) ? ex2f(fmaf(x1, L2E, -rml)) : 0.f;
            lsum[r] += e0 + e1;
            uint32_t hi = packbf2(e1, e0);
            float h0 = __uint_as_float(hi << 16);
            float h1 = __uint_as_float(hi & 0xFFFF0000u);
            uint32_t lo = packbf2(e1 - h1, e0 - h0);
            ehi[row*36 + lane] = hi;
            elo[row*36 + lane] = lo;
        }
        __syncthreads();                         // all operand tiles ready

        // --- mma phase: 16x32 warp tile, k=64 in 4 k16-steps, 3xbf16, zero ALU ---
        const uint32_t* ea_hi = ehi + (16*rg + gid)*36;
        const uint32_t* ea_lo = elo + (16*rg + gid)*36;
        #pragma unroll
        for (int kk = 0; kk < 4; kk++){
            const int kp = 8*kk + t4;
            uint32_t ah[4], al[4];
            ah[0] = ea_hi[kp];          ah[1] = ea_hi[8*36 + kp];
            ah[2] = ea_hi[kp + 4];      ah[3] = ea_hi[8*36 + kp + 4];
            al[0] = ea_lo[kp];          al[1] = ea_lo[8*36 + kp];
            al[2] = ea_lo[kp + 4];      al[3] = ea_lo[8*36 + kp + 4];
            #pragma unroll
            for (int nt = 0; nt < 4; nt++){
                const int cb = (32*fh + 8*nt + gid)*36;
                uint32_t b0 = bhi_s[cb + kp], b1 = bhi_s[cb + kp + 4];
                uint32_t c0 = blo_s[cb + kp], c1 = blo_s[cb + kp + 4];
                mma_bf16(dacc[nt], ah, b0, b1);
                mma_bf16(dacc[nt], ah, c0, c1);
                mma_bf16(dacc[nt], al, b0, b1);
            }
        }
        __syncthreads();                         // protect tiles before next iteration
    }

    // reduce row sums (per-lane partials) and invert
    #pragma unroll
    for (int r = 0; r < 8; r++){
        float v = lsum[r];
        #pragma unroll
        for (int o = 16; o; o >>= 1) v += __shfl_xor_sync(0xffffffffu, v, o);
        if (lane == 0) linv_s[row0 + r] = 1.f / v;
    }
    __syncthreads();

    // epilogue: scale by 1/l, (elu,) store. d-regs: (gid,2t4),(gid,2t4+1),(gid+8,..)
    const int r0 = 16*rg + gid, r1 = r0 + 8;
    const float inv0 = linv_s[r0];
    const float inv1 = linv_s[r1];
    const int ng0 = n0 + r0, ng1 = n0 + r1;
    #pragma unroll
    for (int nt = 0; nt < 4; nt++){
        const int col = 32*fh + 8*nt + 2*t4;
        float v00 = dacc[nt][0]*inv0, v01 = dacc[nt][1]*inv0;
        float v10 = dacc[nt][2]*inv1, v11 = dacc[nt][3]*inv1;
        if (LAYER1){
            v00 = (v00 > 0.f) ? v00 : expm1f(v00);
            v01 = (v01 > 0.f) ? v01 : expm1f(v01);
            v10 = (v10 > 0.f) ? v10 : expm1f(v10);
            v11 = (v11 > 0.f) ? v11 : expm1f(v11);
            float* base = &g_x1[((size_t)(b*CC + c)*NN)*FIN2 + h*FF + col];
            *(float2*)(base + (size_t)ng0*FIN2) = make_float2(v00, v01);
            *(float2*)(base + (size_t)ng1*FIN2) = make_float2(v10, v11);
        } else {
            float* base = &g_o2[((size_t)sl*NN)*FF + col];
            *(float2*)(base + (size_t)ng0*FF) = make_float2(v00, v01);
            *(float2*)(base + (size_t)ng1*FF) = make_float2(v10, v11);
        }
    }
}

// ---------------- kernel 5: mean over heads ----------------
__global__ void reduce_mean_kernel(float* __restrict__ out){
    int idx = blockIdx.x*blockDim.x + threadIdx.x;          // B*C*N*F = 262144
    int f  = idx & 63;
    int nn = (idx >> 6) & (NN - 1);
    int bc = idx >> 16;
    float sum = 0.f;
    #pragma unroll
    for (int h = 0; h < HH; h++)
        sum += g_o2[(((size_t)bc*HH + h)*NN + nn)*FF + f];
    out[idx] = sum * (1.f / HH);
}

// ---------------- launch ----------------
extern "C" void kernel_launch(void* const* d_in, const int* in_sizes, int n_in,
                              void* d_out, int out_size)
{
    const float* x   = (const float*)d_in[0];
    const int*   adj = (const int*)  d_in[1];
    const float* w1  = (const float*)d_in[2];
    const float* as1 = (const float*)d_in[3];
    const float* ad1 = (const float*)d_in[4];
    const float* w2  = (const float*)d_in[5];
    const float* as2 = (const float*)d_in[6];
    const float* ad2 = (const float*)d_in[7];
    float* out = (float*)d_out;

    pack_mask_kernel<<<dim3(NN, BB), 1024>>>(adj);

    gemm_sd_kernel<64,  false><<<dim3(NSL, 16), 256>>>(x, w1, as1, ad1);
    rowmax_kernel<<<dim3(NSL, 8), 256>>>();
    attn_mma_kernel<true ><<<dim3(NSL, 16), 256>>>();

    gemm_sd_kernel<FIN2, true><<<dim3(NSL, 16), 256>>>(nullptr, w2, as2, ad2);
    rowmax_kernel<<<dim3(NSL, 8), 256>>>();
    attn_mma_kernel<false><<<dim3(NSL, 16), 256>>>();

    reduce_mean_kernel<<<(BB*CC*NN*FF)/256, 256>>>(out);
}